// round 15
// baseline (speedup 1.0000x reference)
#include <cuda_runtime.h>
#include <cuda_bf16.h>
#include <math.h>
#include <stdint.h>

#define NMAX 100000
#define HDIM 128
#define EMAX 625000
#define NEG_SLOPE 0.2f
#define KPAD 136                 // W image row stride (bf16 elems), 272B
#define APADB 80                 // A smem row stride bytes (40 bf16)
#define WIMG_BYTES 34816         // one 128xKPAD bf16 image

// ---------------- scratch ---------------------------------------------------------
__device__ float g_xs[NMAX * HDIM];
__device__ float g_xd[NMAX * HDIM];
__device__ float g_acc[NMAX * HDIM];
__device__ float g_h[NMAX * HDIM];
__device__ float g_sum[HDIM];
__device__ float g_sumsq[HDIM];
__device__ __align__(16) __nv_bfloat16 g_Wbf[6 * 2 * 128 * KPAD];  // [mat][hi/lo][n][k]

// CSR scratch
__device__ int g_deg[NMAX];
__device__ int g_fill[NMAX];
__device__ int g_rowptr[NMAX + 1];
__device__ int g_col[EMAX];
__device__ int g_blocksum[128];

// ---------------- helpers ----------------------------------------------------------
__device__ __forceinline__ uint32_t smem_to_u32(const void* p) {
    uint32_t a;
    asm("{ .reg .u64 t; cvta.to.shared.u64 t, %1; cvt.u32.u64 %0, t; }" : "=r"(a) : "l"(p));
    return a;
}
__device__ __forceinline__ void ldsm_x4(uint32_t& r0, uint32_t& r1, uint32_t& r2,
                                        uint32_t& r3, uint32_t addr) {
    asm volatile("ldmatrix.sync.aligned.m8n8.x4.shared.b16 {%0,%1,%2,%3}, [%4];"
                 : "=r"(r0), "=r"(r1), "=r"(r2), "=r"(r3) : "r"(addr));
}
__device__ __forceinline__ void mma_bf16(float* c, const uint32_t* a, const uint32_t* b) {
    asm volatile(
        "mma.sync.aligned.m16n8k16.row.col.f32.bf16.bf16.f32 "
        "{%0,%1,%2,%3}, {%4,%5,%6,%7}, {%8,%9}, {%0,%1,%2,%3};"
        : "+f"(c[0]), "+f"(c[1]), "+f"(c[2]), "+f"(c[3])
        : "r"(a[0]), "r"(a[1]), "r"(a[2]), "r"(a[3]), "r"(b[0]), "r"(b[1]));
}
__device__ __forceinline__ uint32_t pack_hi(float x, float y) {
    __nv_bfloat16 h0 = __float2bfloat16(x), h1 = __float2bfloat16(y);
    return (uint32_t)__bfloat16_as_ushort(h0) | ((uint32_t)__bfloat16_as_ushort(h1) << 16);
}
__device__ __forceinline__ uint32_t pack_lo(float x, float y) {
    __nv_bfloat16 h0 = __float2bfloat16(x), h1 = __float2bfloat16(y);
    __nv_bfloat16 l0 = __float2bfloat16(x - __bfloat162float(h0));
    __nv_bfloat16 l1 = __float2bfloat16(y - __bfloat162float(h1));
    return (uint32_t)__bfloat16_as_ushort(l0) | ((uint32_t)__bfloat16_as_ushort(l1) << 16);
}

// ---------------- prep: W transpose/split ----------------------------------------------
__global__ void prep_w_kernel(const float* __restrict__ Wl, const float* __restrict__ Wr,
                              const float* __restrict__ Wlin, int n) {
    int idx = blockIdx.x * blockDim.x + threadIdx.x;
    if (idx >= 6 * 128 * 128) return;
    int m = idx >> 14;
    int r = idx & 16383;
    int nrow = r >> 7;
    int k = r & 127;
    int layer = m / 3, which = m % 3;
    const float* W = (which == 0 ? Wl : which == 1 ? Wr : Wlin) + (size_t)layer * HDIM * HDIM;
    float w = W[k * 128 + nrow];
    __nv_bfloat16 h = __float2bfloat16(w);
    __nv_bfloat16 l = __float2bfloat16(w - __bfloat162float(h));
    g_Wbf[((size_t)(m * 2 + 0) * 128 + nrow) * KPAD + k] = h;
    g_Wbf[((size_t)(m * 2 + 1) * 128 + nrow) * KPAD + k] = l;
}

// CSR zero (side stream)
__global__ void csr_zero_kernel(int n) {
    int i = blockIdx.x * blockDim.x + threadIdx.x;
    if (i < n) { g_deg[i] = 0; g_fill[i] = 0; }
}

// ---------------- dual GEMM: xs = f(X)@Wl + bl, xd = f(X)@Wr + br ---------------------
#define DSM_AH 0
#define DSM_AL 10240
#define DSM_BH 20480
#define DSM_BL (DSM_BH + 2 * WIMG_BYTES)
#define DSM_TOTAL (DSM_BL + 2 * WIMG_BYTES)

__global__ __launch_bounds__(512, 1) void gemm_dual_kernel(
    const float* __restrict__ X, int wimgL, int wimgR,
    const float* __restrict__ biasL, const float* __restrict__ biasR,
    float* __restrict__ YL, float* __restrict__ YR, int n, int mode,
    const float* __restrict__ bng, const float* __restrict__ bnb)
{
    extern __shared__ char smem[];
    __shared__ float s_scale[128];
    __shared__ float s_shift[128];
    const uint32_t sb = smem_to_u32(smem);
    const int tid = threadIdx.x;
    const int wid = tid >> 5;
    const int lane = tid & 31;
    const int row0 = blockIdx.x * 128;
    const int warp_m = wid & 3;
    const int warp_n = wid >> 2;

    if (mode == 2 && tid < 128) {
        float inv_n = 1.0f / (float)n;
        float mu = g_sum[tid] * inv_n;
        float var = g_sumsq[tid] * inv_n - mu * mu;
        float sc = bng[tid] * rsqrtf(var + 1e-5f);
        s_scale[tid] = sc;
        s_shift[tid] = bnb[tid] - mu * sc;
    }

    {
        const uint4* gLh = (const uint4*)(g_Wbf + (size_t)(wimgL * 2 + 0) * 128 * KPAD);
        const uint4* gLl = (const uint4*)(g_Wbf + (size_t)(wimgL * 2 + 1) * 128 * KPAD);
        const uint4* gRh = (const uint4*)(g_Wbf + (size_t)(wimgR * 2 + 0) * 128 * KPAD);
        const uint4* gRl = (const uint4*)(g_Wbf + (size_t)(wimgR * 2 + 1) * 128 * KPAD);
        uint4* sBh = (uint4*)(smem + DSM_BH);
        uint4* sBl = (uint4*)(smem + DSM_BL);
        for (int f = tid; f < 2176; f += 512) {
            sBh[f] = gLh[f];
            sBh[f + 2176] = gRh[f];
            sBl[f] = gLl[f];
            sBl[f + 2176] = gRl[f];
        }
    }

    float4 pre[2];
#pragma unroll
    for (int i = 0; i < 2; i++) {
        int f = tid + i * 512;
        int row = f >> 3, c4 = (f & 7) * 4;
        int gr = row0 + row;
        pre[i] = (gr < n) ? *(const float4*)&X[(size_t)gr * 128 + c4]
                          : make_float4(0.f, 0.f, 0.f, 0.f);
    }
    __syncthreads();

    float acc[2][8][4];
#pragma unroll
    for (int a = 0; a < 2; a++)
#pragma unroll
        for (int b = 0; b < 8; b++)
#pragma unroll
            for (int c = 0; c < 4; c++) acc[a][b][c] = 0.0f;

    const uint32_t aAh = sb + DSM_AH + (warp_m * 32 + (lane & 15)) * APADB + (lane >> 4) * 16;
    const uint32_t aAl = aAh + (DSM_AL - DSM_AH);
    const uint32_t aBh = sb + DSM_BH + (warp_n >> 1) * WIMG_BYTES
                       + ((warp_n & 1) * 64 + (lane & 7) + (lane >> 4) * 8) * (KPAD * 2)
                       + ((lane >> 3) & 1) * 16;
    const uint32_t aBl = aBh + (DSM_BL - DSM_BH);

    for (int kc = 0; kc < 128; kc += 32) {
#pragma unroll
        for (int i = 0; i < 2; i++) {
            int f = tid + i * 512;
            int row = f >> 3, c4 = (f & 7) * 4;
            float4 v = pre[i];
            if (mode == 2) {
                int cc = kc + c4;
                v.x = fmaxf(0.f, fmaf(v.x, s_scale[cc],     s_shift[cc]));
                v.y = fmaxf(0.f, fmaf(v.y, s_scale[cc + 1], s_shift[cc + 1]));
                v.z = fmaxf(0.f, fmaf(v.z, s_scale[cc + 2], s_shift[cc + 2]));
                v.w = fmaxf(0.f, fmaf(v.w, s_scale[cc + 3], s_shift[cc + 3]));
            }
            *(uint2*)(smem + DSM_AH + row * APADB + c4 * 2) =
                make_uint2(pack_hi(v.x, v.y), pack_hi(v.z, v.w));
            *(uint2*)(smem + DSM_AL + row * APADB + c4 * 2) =
                make_uint2(pack_lo(v.x, v.y), pack_lo(v.z, v.w));
        }
        __syncthreads();

        if (kc < 96) {
#pragma unroll
            for (int i = 0; i < 2; i++) {
                int f = tid + i * 512;
                int row = f >> 3, c4 = (f & 7) * 4;
                int gr = row0 + row;
                pre[i] = (gr < n) ? *(const float4*)&X[(size_t)gr * 128 + kc + 32 + c4]
                                  : make_float4(0.f, 0.f, 0.f, 0.f);
            }
        }

#pragma unroll
        for (int kk = 0; kk < 32; kk += 16) {
            uint32_t ah[2][4], al[2][4];
#pragma unroll
            for (int ms = 0; ms < 2; ms++) {
                uint32_t off = ms * 16 * APADB + kk * 2;
                ldsm_x4(ah[ms][0], ah[ms][1], ah[ms][2], ah[ms][3], aAh + off);
                ldsm_x4(al[ms][0], al[ms][1], al[ms][2], al[ms][3], aAl + off);
            }
#pragma unroll
            for (int nn = 0; nn < 4; nn++) {
                uint32_t bh2[4], bl2[4];
                uint32_t off = nn * 16 * (KPAD * 2) + (kc + kk) * 2;
                ldsm_x4(bh2[0], bh2[1], bh2[2], bh2[3], aBh + off);
                ldsm_x4(bl2[0], bl2[1], bl2[2], bl2[3], aBl + off);
#pragma unroll
                for (int ms = 0; ms < 2; ms++) {
                    mma_bf16(acc[ms][nn * 2],     ah[ms], bh2);
                    mma_bf16(acc[ms][nn * 2],     al[ms], bh2);
                    mma_bf16(acc[ms][nn * 2],     ah[ms], bl2);
                    mma_bf16(acc[ms][nn * 2 + 1], ah[ms], bh2 + 2);
                    mma_bf16(acc[ms][nn * 2 + 1], al[ms], bh2 + 2);
                    mma_bf16(acc[ms][nn * 2 + 1], ah[ms], bl2 + 2);
                }
            }
        }
        if (kc < 96) __syncthreads();
    }

    float* Y = (warp_n < 2) ? YL : YR;
    const float* bias = (warp_n < 2) ? biasL : biasR;
    const int er0 = row0 + warp_m * 32 + (lane >> 2);
    const int ec0 = (warp_n & 1) * 64 + (lane & 3) * 2;
#pragma unroll
    for (int ms = 0; ms < 2; ms++) {
#pragma unroll
        for (int ns = 0; ns < 8; ns++) {
            int r = er0 + ms * 16;
            int c = ec0 + ns * 8;
            float b0 = __ldg(&bias[c]), b1 = __ldg(&bias[c + 1]);
            if (r < n)
                *(float2*)&Y[(size_t)r * 128 + c] =
                    make_float2(acc[ms][ns][0] + b0, acc[ms][ns][1] + b1);
            if (r + 8 < n)
                *(float2*)&Y[(size_t)(r + 8) * 128 + c] =
                    make_float2(acc[ms][ns][2] + b0, acc[ms][ns][3] + b1);
        }
    }
}

// ---------------- GEMM v5 (residual + fused BN stats): Y = X + X@W + b ----------------
#define SM4_AH 0
#define SM4_AL 10240
#define SM4_BH 20480
#define SM4_BL 55296
#define SM4_TOTAL 90112

__global__ __launch_bounds__(256, 2) void gemm_mma4_kernel(
    const float* __restrict__ X, int wimg, const float* __restrict__ bias,
    float* __restrict__ Y, int n)
{
    extern __shared__ char smem[];
    const uint32_t sb = smem_to_u32(smem);
    const int tid = threadIdx.x;
    const int wid = tid >> 5;
    const int lane = tid & 31;
    const int row0 = blockIdx.x * 128;
    const int warp_m = wid & 3;
    const int warp_n = wid >> 2;

    {
        const uint4* gBh = (const uint4*)(g_Wbf + (size_t)(wimg * 2 + 0) * 128 * KPAD);
        const uint4* gBl = (const uint4*)(g_Wbf + (size_t)(wimg * 2 + 1) * 128 * KPAD);
        uint4* sBh = (uint4*)(smem + SM4_BH);
        uint4* sBl = (uint4*)(smem + SM4_BL);
        for (int f = tid; f < 2176; f += 256) {
            sBh[f] = gBh[f];
            sBl[f] = gBl[f];
        }
    }

    float4 pre[4];
#pragma unroll
    for (int i = 0; i < 4; i++) {
        int f = tid + i * 256;
        int row = f >> 3, c4 = (f & 7) * 4;
        int gr = row0 + row;
        pre[i] = (gr < n) ? *(const float4*)&X[(size_t)gr * 128 + c4]
                          : make_float4(0.f, 0.f, 0.f, 0.f);
    }
    __syncthreads();

    float acc[2][8][4];
#pragma unroll
    for (int a = 0; a < 2; a++)
#pragma unroll
        for (int b = 0; b < 8; b++)
#pragma unroll
            for (int c = 0; c < 4; c++) acc[a][b][c] = 0.0f;

    const uint32_t aAh = sb + SM4_AH + (warp_m * 32 + (lane & 15)) * APADB + (lane >> 4) * 16;
    const uint32_t aAl = aAh + (SM4_AL - SM4_AH);
    const uint32_t aBh = sb + SM4_BH + (warp_n * 64 + (lane & 7) + (lane >> 4) * 8) * (KPAD * 2)
                       + ((lane >> 3) & 1) * 16;
    const uint32_t aBl = aBh + (SM4_BL - SM4_BH);

    for (int kc = 0; kc < 128; kc += 32) {
#pragma unroll
        for (int i = 0; i < 4; i++) {
            int f = tid + i * 256;
            int row = f >> 3, c4 = (f & 7) * 4;
            float4 v = pre[i];
            *(uint2*)(smem + SM4_AH + row * APADB + c4 * 2) =
                make_uint2(pack_hi(v.x, v.y), pack_hi(v.z, v.w));
            *(uint2*)(smem + SM4_AL + row * APADB + c4 * 2) =
                make_uint2(pack_lo(v.x, v.y), pack_lo(v.z, v.w));
        }
        __syncthreads();

        if (kc < 96) {
#pragma unroll
            for (int i = 0; i < 4; i++) {
                int f = tid + i * 256;
                int row = f >> 3, c4 = (f & 7) * 4;
                int gr = row0 + row;
                pre[i] = (gr < n) ? *(const float4*)&X[(size_t)gr * 128 + kc + 32 + c4]
                                  : make_float4(0.f, 0.f, 0.f, 0.f);
            }
        }

#pragma unroll
        for (int kk = 0; kk < 32; kk += 16) {
            uint32_t ah[2][4], al[2][4];
#pragma unroll
            for (int ms = 0; ms < 2; ms++) {
                uint32_t off = ms * 16 * APADB + kk * 2;
                ldsm_x4(ah[ms][0], ah[ms][1], ah[ms][2], ah[ms][3], aAh + off);
                ldsm_x4(al[ms][0], al[ms][1], al[ms][2], al[ms][3], aAl + off);
            }
#pragma unroll
            for (int nn = 0; nn < 4; nn++) {
                uint32_t bh2[4], bl2[4];
                uint32_t off = nn * 16 * (KPAD * 2) + (kc + kk) * 2;
                ldsm_x4(bh2[0], bh2[1], bh2[2], bh2[3], aBh + off);
                ldsm_x4(bl2[0], bl2[1], bl2[2], bl2[3], aBl + off);
#pragma unroll
                for (int ms = 0; ms < 2; ms++) {
                    mma_bf16(acc[ms][nn * 2],     ah[ms], bh2);
                    mma_bf16(acc[ms][nn * 2],     al[ms], bh2);
                    mma_bf16(acc[ms][nn * 2],     ah[ms], bl2);
                    mma_bf16(acc[ms][nn * 2 + 1], ah[ms], bh2 + 2);
                    mma_bf16(acc[ms][nn * 2 + 1], al[ms], bh2 + 2);
                    mma_bf16(acc[ms][nn * 2 + 1], ah[ms], bl2 + 2);
                }
            }
        }
        if (kc < 96) __syncthreads();
    }

    // epilogue with fused BN stats (column sum / sumsq)
    float cs[16], cq[16];
#pragma unroll
    for (int j = 0; j < 16; j++) { cs[j] = 0.f; cq[j] = 0.f; }

    const int er0 = row0 + warp_m * 32 + (lane >> 2);
    const int ec0 = warp_n * 64 + (lane & 3) * 2;
#pragma unroll
    for (int ms = 0; ms < 2; ms++) {
#pragma unroll
        for (int ns = 0; ns < 8; ns++) {
            int r = er0 + ms * 16;
            int c = ec0 + ns * 8;
            float b0 = __ldg(&bias[c]), b1 = __ldg(&bias[c + 1]);
            if (r < n) {
                const float2 rv = *(const float2*)&X[(size_t)r * 128 + c];
                float o0 = acc[ms][ns][0] + b0 + rv.x;
                float o1 = acc[ms][ns][1] + b1 + rv.y;
                *(float2*)&Y[(size_t)r * 128 + c] = make_float2(o0, o1);
                cs[ns * 2] += o0; cq[ns * 2] += o0 * o0;
                cs[ns * 2 + 1] += o1; cq[ns * 2 + 1] += o1 * o1;
            }
            if (r + 8 < n) {
                const float2 rv = *(const float2*)&X[(size_t)(r + 8) * 128 + c];
                float o0 = acc[ms][ns][2] + b0 + rv.x;
                float o1 = acc[ms][ns][3] + b1 + rv.y;
                *(float2*)&Y[(size_t)(r + 8) * 128 + c] = make_float2(o0, o1);
                cs[ns * 2] += o0; cq[ns * 2] += o0 * o0;
                cs[ns * 2 + 1] += o1; cq[ns * 2 + 1] += o1 * o1;
            }
        }
    }

#pragma unroll
    for (int o = 4; o <= 16; o <<= 1) {
#pragma unroll
        for (int j = 0; j < 16; j++) {
            cs[j] += __shfl_xor_sync(0xffffffff, cs[j], o);
            cq[j] += __shfl_xor_sync(0xffffffff, cq[j], o);
        }
    }
    __syncthreads();
    float (*sred)[4][32] = (float (*)[4][32])(smem + SM4_AH);
    if (lane < 4) {
#pragma unroll
        for (int j = 0; j < 16; j++) {
            sred[wid][lane][j] = cs[j];
            sred[wid][lane][16 + j] = cq[j];
        }
    }
    __syncthreads();
    {
        int stat = tid >> 7;
        int col = tid & 127;
        int wn = col >> 6;
        int lane_sel = (col >> 1) & 3;
        int nss = (col & 63) >> 3;
        int j0 = nss * 2 + (col & 1);
        int idx = stat * 16 + j0;
        float t = sred[wn * 4 + 0][lane_sel][idx] + sred[wn * 4 + 1][lane_sel][idx]
                + sred[wn * 4 + 2][lane_sel][idx] + sred[wn * 4 + 3][lane_sel][idx];
        if (stat == 0) atomicAdd(&g_sum[col], t);
        else           atomicAdd(&g_sumsq[col], t);
    }
}

// ---------------- CSR build ------------------------------------------------------
__global__ void csr_hist_kernel(const int* __restrict__ dst, int E) {
    int e = blockIdx.x * blockDim.x + threadIdx.x;
    if (e < E) atomicAdd(&g_deg[dst[e]], 1);
}
__global__ void csr_scanA_kernel(int n) {
    __shared__ int s[1024];
    int t = threadIdx.x;
    int i = blockIdx.x * 1024 + t;
    int v = (i < n) ? g_deg[i] : 0;
    s[t] = v;
    __syncthreads();
#pragma unroll
    for (int off = 1; off < 1024; off <<= 1) {
        int x = (t >= off) ? s[t - off] : 0;
        __syncthreads();
        s[t] += x;
        __syncthreads();
    }
    if (i < n) g_rowptr[i + 1] = s[t];
    if (t == 1023) g_blocksum[blockIdx.x] = s[t];
    if (i == 0) g_rowptr[0] = 0;
}
__global__ void csr_scanC_kernel(int n) {
    __shared__ int s_off;
    int t = threadIdx.x;
    if (t < 32) {
        int b = blockIdx.x;
        int sum = 0;
        for (int i = t; i < b; i += 32) sum += g_blocksum[i];
#pragma unroll
        for (int o = 16; o; o >>= 1) sum += __shfl_xor_sync(0xffffffff, sum, o);
        if (t == 0) s_off = sum;
    }
    __syncthreads();
    int i = blockIdx.x * 1024 + t;
    if (i < n) g_rowptr[i + 1] += s_off;
}
__global__ void csr_fill_kernel(const int* __restrict__ src, const int* __restrict__ dst, int E) {
    int e = blockIdx.x * blockDim.x + threadIdx.x;
    if (e < E) {
        int d = dst[e];
        int pos = g_rowptr[d] + atomicAdd(&g_fill[d], 1);
        g_col[pos] = src[e];
    }
}

// ---------------- aggregation v5: half-warp per edge, 4-level butterfly ---------------
__device__ __forceinline__ float dot_leaky(float4 xs4, float4 xd4, float4 at4) {
    float t, p = 0.0f;
    t = xs4.x + xd4.x; t = t > 0.f ? t : NEG_SLOPE * t; p = fmaf(t, at4.x, p);
    t = xs4.y + xd4.y; t = t > 0.f ? t : NEG_SLOPE * t; p = fmaf(t, at4.y, p);
    t = xs4.z + xd4.z; t = t > 0.f ? t : NEG_SLOPE * t; p = fmaf(t, at4.z, p);
    t = xs4.w + xd4.w; t = t > 0.f ? t : NEG_SLOPE * t; p = fmaf(t, at4.w, p);
    return p;
}

__global__ __launch_bounds__(256) void agg_kernel(
    const float* __restrict__ att, const float* __restrict__ cb, int n)
{
    if (blockIdx.x == 0 && threadIdx.x < HDIM) {
        g_sum[threadIdx.x] = 0.0f;
        g_sumsq[threadIdx.x] = 0.0f;
    }
    int d = (blockIdx.x * blockDim.x + threadIdx.x) >> 5;
    int lane = threadIdx.x & 31;
    if (d >= n) return;

    const int half = lane >> 4;         // which edge of the pair
    const int hl = lane & 15;           // 16 lanes cover the 128 features, 8 each
    const int fb = hl * 8;              // feature base for this lane

    float4 xd0 = *(const float4*)&g_xd[(size_t)d * 128 + fb];
    float4 xd1 = *(const float4*)&g_xd[(size_t)d * 128 + fb + 4];
    float4 at0 = *(const float4*)&att[fb];
    float4 at1 = *(const float4*)&att[fb + 4];

    int e0 = g_rowptr[d], e1 = g_rowptr[d + 1];

    float den = 0.0f;
    float4 acc0 = make_float4(0.f, 0.f, 0.f, 0.f);
    float4 acc1 = make_float4(0.f, 0.f, 0.f, 0.f);

    if (e0 < e1) {
        // prologue: gather this half's first edge (clamped; masked by w=0 later)
        int eh = e0 + half;
        int s = (eh < e1) ? g_col[eh] : g_col[e0];
        float4 a0 = *(const float4*)&g_xs[(size_t)s * 128 + fb];
        float4 a1 = *(const float4*)&g_xs[(size_t)s * 128 + fb + 4];

        for (int e = e0; e < e1; e += 2) {
            float4 c0 = a0, c1 = a1;
            bool valid = (e + half) < e1;
            // prefetch next pair's gathers; latency overlaps the chain below
            if (e + 2 < e1) {
                int eh2 = e + 2 + half;
                int s2 = (eh2 < e1) ? g_col[eh2] : g_col[e0];
                a0 = *(const float4*)&g_xs[(size_t)s2 * 128 + fb];
                a1 = *(const float4*)&g_xs[(size_t)s2 * 128 + fb + 4];
            }
            float p = dot_leaky(c0, xd0, at0) + dot_leaky(c1, xd1, at1);
            // 4-level butterfly within each 16-lane half
#pragma unroll
            for (int o = 8; o; o >>= 1) p += __shfl_xor_sync(0xffffffff, p, o);
            float w = valid ? __expf(p) : 0.0f;
            den += w;
            acc0.x = fmaf(w, c0.x, acc0.x);
            acc0.y = fmaf(w, c0.y, acc0.y);
            acc0.z = fmaf(w, c0.z, acc0.z);
            acc0.w = fmaf(w, c0.w, acc0.w);
            acc1.x = fmaf(w, c1.x, acc1.x);
            acc1.y = fmaf(w, c1.y, acc1.y);
            acc1.z = fmaf(w, c1.z, acc1.z);
            acc1.w = fmaf(w, c1.w, acc1.w);
        }
        // combine the two halves (lane i and i+16 hold the same features)
        den += __shfl_xor_sync(0xffffffff, den, 16);
        acc0.x += __shfl_xor_sync(0xffffffff, acc0.x, 16);
        acc0.y += __shfl_xor_sync(0xffffffff, acc0.y, 16);
        acc0.z += __shfl_xor_sync(0xffffffff, acc0.z, 16);
        acc0.w += __shfl_xor_sync(0xffffffff, acc0.w, 16);
        acc1.x += __shfl_xor_sync(0xffffffff, acc1.x, 16);
        acc1.y += __shfl_xor_sync(0xffffffff, acc1.y, 16);
        acc1.z += __shfl_xor_sync(0xffffffff, acc1.z, 16);
        acc1.w += __shfl_xor_sync(0xffffffff, acc1.w, 16);
    }

    if (half == 0) {
        float inv = 1.0f / (den + 1e-16f);
        float4 cb0 = *(const float4*)&cb[fb];
        float4 cb1 = *(const float4*)&cb[fb + 4];
        float4 o0, o1;
        o0.x = acc0.x * inv + cb0.x;
        o0.y = acc0.y * inv + cb0.y;
        o0.z = acc0.z * inv + cb0.z;
        o0.w = acc0.w * inv + cb0.w;
        o1.x = acc1.x * inv + cb1.x;
        o1.y = acc1.y * inv + cb1.y;
        o1.z = acc1.z * inv + cb1.z;
        o1.w = acc1.w * inv + cb1.w;
        *(float4*)&g_acc[(size_t)d * 128 + fb]     = o0;
        *(float4*)&g_acc[(size_t)d * 128 + fb + 4] = o1;
    }
}

// ---------------- BN apply (final output, float4) ---------------------------------------
__global__ __launch_bounds__(256) void bn_apply_kernel(
    const float* __restrict__ gamma, const float* __restrict__ beta,
    float* __restrict__ out, int n)
{
    int i = blockIdx.x * blockDim.x + threadIdx.x;       // one float4 per thread
    if (i >= n * 32) return;
    int h4 = (i & 31) * 4;
    float inv_n = 1.0f / (float)n;
    float4 v = *(const float4*)&g_h[(size_t)i * 4];
    float4 o;
#pragma unroll
    for (int j = 0; j < 4; j++) {
        int h = h4 + j;
        float mu = g_sum[h] * inv_n;
        float var = g_sumsq[h] * inv_n - mu * mu;
        float val = ((&v.x)[j] - mu) * rsqrtf(var + 1e-5f) * gamma[h] + beta[h];
        (&o.x)[j] = val;
    }
    *(float4*)&out[(size_t)i * 4] = o;
}

// ---------------- host driver ---------------------------------------------------------
extern "C" void kernel_launch(void* const* d_in, const int* in_sizes, int n_in,
                              void* d_out, int out_size)
{
    const float* x     = (const float*)d_in[0];
    const int*   ei    = (const int*)  d_in[1];
    const float* Wl    = (const float*)d_in[2];
    const float* bl    = (const float*)d_in[3];
    const float* Wr    = (const float*)d_in[4];
    const float* br    = (const float*)d_in[5];
    const float* att   = (const float*)d_in[6];
    const float* cb    = (const float*)d_in[7];
    const float* Wlin  = (const float*)d_in[8];
    const float* blin  = (const float*)d_in[9];
    const float* gamma = (const float*)d_in[10];
    const float* beta  = (const float*)d_in[11];

    const int n = in_sizes[0] / HDIM;
    const int E = in_sizes[1] / 2;
    const int* src = ei;
    const int* dst = ei + E;

    void* p;
    cudaGetSymbolAddress(&p, g_acc); float* p_acc = (float*)p;
    cudaGetSymbolAddress(&p, g_xs);  float* p_xs  = (float*)p;
    cudaGetSymbolAddress(&p, g_xd);  float* p_xd  = (float*)p;
    cudaGetSymbolAddress(&p, g_h);   float* p_h   = (float*)p;

    static cudaStream_t s2 = nullptr;
    static cudaEvent_t ev_fork = nullptr, ev_join = nullptr;
    if (!s2) {
        cudaStreamCreateWithFlags(&s2, cudaStreamNonBlocking);
        cudaEventCreateWithFlags(&ev_fork, cudaEventDisableTiming);
        cudaEventCreateWithFlags(&ev_join, cudaEventDisableTiming);
        cudaFuncSetAttribute(gemm_mma4_kernel, cudaFuncAttributeMaxDynamicSharedMemorySize,
                             SM4_TOTAL);
        cudaFuncSetAttribute(gemm_dual_kernel, cudaFuncAttributeMaxDynamicSharedMemorySize,
                             DSM_TOTAL);
    }

    const int gemm_blocks = (n + 127) / 128;
    const int agg_blocks  = (n + 7) / 8;
    const int e_blocks    = (E + 255) / 256;
    const int scan_blocks = (n + 1023) / 1024;
    const int prep_blocks = (6 * 128 * 128 + 255) / 256;
    const int bn4_blocks  = (n * 32 + 255) / 256;

    // fork: CSR build on side stream, overlapped with prep_w + layer-0 dual GEMM
    cudaEventRecord(ev_fork, 0);
    cudaStreamWaitEvent(s2, ev_fork, 0);
    csr_zero_kernel<<<(n + 255) / 256, 256, 0, s2>>>(n);
    csr_hist_kernel<<<e_blocks, 256, 0, s2>>>(dst, E);
    csr_scanA_kernel<<<scan_blocks, 1024, 0, s2>>>(n);
    csr_scanC_kernel<<<scan_blocks, 1024, 0, s2>>>(n);
    csr_fill_kernel<<<e_blocks, 256, 0, s2>>>(src, dst, E);
    cudaEventRecord(ev_join, s2);

    // main stream: weight prep + layer-0 transforms
    prep_w_kernel<<<prep_blocks, 256>>>(Wl, Wr, Wlin, n);
    gemm_dual_kernel<<<gemm_blocks, 512, DSM_TOTAL>>>(x, 0, 1, bl, br, p_xs, p_xd,
                                                      n, 0, nullptr, nullptr);

    // join: agg needs the CSR
    cudaStreamWaitEvent(0, ev_join, 0);

    // layer 0
    agg_kernel<<<agg_blocks, 256>>>(att, cb, n);
    gemm_mma4_kernel<<<gemm_blocks, 256, SM4_TOTAL>>>(p_acc, 2, blin, p_h, n);

    // layer 1 (BN+relu of layer-0 output fused into dual A-staging)
    gemm_dual_kernel<<<gemm_blocks, 512, DSM_TOTAL>>>(p_h, 3, 4, bl + HDIM, br + HDIM,
                                                      p_xs, p_xd, n, 2, gamma, beta);
    agg_kernel<<<agg_blocks, 256>>>(att + HDIM, cb + HDIM, n);
    gemm_mma4_kernel<<<gemm_blocks, 256, SM4_TOTAL>>>(p_acc, 5, blin + HDIM, p_h, n);
    bn_apply_kernel<<<bn4_blocks, 256>>>(gamma + HDIM, beta + HDIM, (float*)d_out, n);
}

// round 16
// speedup vs baseline: 1.0538x; 1.0538x over previous
#include <cuda_runtime.h>
#include <cuda_bf16.h>
#include <math.h>
#include <stdint.h>

#define NMAX 100000
#define HDIM 128
#define EMAX 625000
#define NEG_SLOPE 0.2f
#define KPAD 136                 // W image row stride (bf16 elems), 272B
#define APADB 80                 // A smem row stride bytes (40 bf16)
#define WIMG_BYTES 34816         // one 128xKPAD bf16 image

// ---------------- scratch ---------------------------------------------------------
__device__ float g_xs[NMAX * HDIM];
__device__ float g_xd[NMAX * HDIM];
__device__ float g_acc[NMAX * HDIM];
__device__ float g_h[NMAX * HDIM];
__device__ float g_sum[HDIM];
__device__ float g_sumsq[HDIM];
__device__ __align__(16) __nv_bfloat16 g_Wbf[6 * 2 * 128 * KPAD];  // [mat][hi/lo][n][k]

// CSR scratch
__device__ int g_deg[NMAX];
__device__ int g_fill[NMAX];
__device__ int g_rowptr[NMAX + 1];
__device__ int g_col[EMAX];
__device__ int g_blocksum[128];

// ---------------- helpers ----------------------------------------------------------
__device__ __forceinline__ uint32_t smem_to_u32(const void* p) {
    uint32_t a;
    asm("{ .reg .u64 t; cvta.to.shared.u64 t, %1; cvt.u32.u64 %0, t; }" : "=r"(a) : "l"(p));
    return a;
}
__device__ __forceinline__ void ldsm_x4(uint32_t& r0, uint32_t& r1, uint32_t& r2,
                                        uint32_t& r3, uint32_t addr) {
    asm volatile("ldmatrix.sync.aligned.m8n8.x4.shared.b16 {%0,%1,%2,%3}, [%4];"
                 : "=r"(r0), "=r"(r1), "=r"(r2), "=r"(r3) : "r"(addr));
}
__device__ __forceinline__ void mma_bf16(float* c, const uint32_t* a, const uint32_t* b) {
    asm volatile(
        "mma.sync.aligned.m16n8k16.row.col.f32.bf16.bf16.f32 "
        "{%0,%1,%2,%3}, {%4,%5,%6,%7}, {%8,%9}, {%0,%1,%2,%3};"
        : "+f"(c[0]), "+f"(c[1]), "+f"(c[2]), "+f"(c[3])
        : "r"(a[0]), "r"(a[1]), "r"(a[2]), "r"(a[3]), "r"(b[0]), "r"(b[1]));
}
__device__ __forceinline__ uint32_t pack_hi(float x, float y) {
    __nv_bfloat16 h0 = __float2bfloat16(x), h1 = __float2bfloat16(y);
    return (uint32_t)__bfloat16_as_ushort(h0) | ((uint32_t)__bfloat16_as_ushort(h1) << 16);
}
__device__ __forceinline__ uint32_t pack_lo(float x, float y) {
    __nv_bfloat16 h0 = __float2bfloat16(x), h1 = __float2bfloat16(y);
    __nv_bfloat16 l0 = __float2bfloat16(x - __bfloat162float(h0));
    __nv_bfloat16 l1 = __float2bfloat16(y - __bfloat162float(h1));
    return (uint32_t)__bfloat16_as_ushort(l0) | ((uint32_t)__bfloat16_as_ushort(l1) << 16);
}

// ---------------- prep: W transpose/split ----------------------------------------------
__global__ void prep_w_kernel(const float* __restrict__ Wl, const float* __restrict__ Wr,
                              const float* __restrict__ Wlin, int n) {
    int idx = blockIdx.x * blockDim.x + threadIdx.x;
    if (idx >= 6 * 128 * 128) return;
    int m = idx >> 14;
    int r = idx & 16383;
    int nrow = r >> 7;
    int k = r & 127;
    int layer = m / 3, which = m % 3;
    const float* W = (which == 0 ? Wl : which == 1 ? Wr : Wlin) + (size_t)layer * HDIM * HDIM;
    float w = W[k * 128 + nrow];
    __nv_bfloat16 h = __float2bfloat16(w);
    __nv_bfloat16 l = __float2bfloat16(w - __bfloat162float(h));
    g_Wbf[((size_t)(m * 2 + 0) * 128 + nrow) * KPAD + k] = h;
    g_Wbf[((size_t)(m * 2 + 1) * 128 + nrow) * KPAD + k] = l;
}

// CSR zero (side stream)
__global__ void csr_zero_kernel(int n) {
    int i = blockIdx.x * blockDim.x + threadIdx.x;
    if (i < n) { g_deg[i] = 0; g_fill[i] = 0; }
}

// ---------------- dual GEMM: xs = f(X)@Wl + bl, xd = f(X)@Wr + br ---------------------
#define DSM_AH 0
#define DSM_AL 10240
#define DSM_BH 20480
#define DSM_BL (DSM_BH + 2 * WIMG_BYTES)
#define DSM_TOTAL (DSM_BL + 2 * WIMG_BYTES)

__global__ __launch_bounds__(512, 1) void gemm_dual_kernel(
    const float* __restrict__ X, int wimgL, int wimgR,
    const float* __restrict__ biasL, const float* __restrict__ biasR,
    float* __restrict__ YL, float* __restrict__ YR, int n, int mode,
    const float* __restrict__ bng, const float* __restrict__ bnb)
{
    extern __shared__ char smem[];
    __shared__ float s_scale[128];
    __shared__ float s_shift[128];
    const uint32_t sb = smem_to_u32(smem);
    const int tid = threadIdx.x;
    const int wid = tid >> 5;
    const int lane = tid & 31;
    const int row0 = blockIdx.x * 128;
    const int warp_m = wid & 3;
    const int warp_n = wid >> 2;

    if (mode == 2 && tid < 128) {
        float inv_n = 1.0f / (float)n;
        float mu = g_sum[tid] * inv_n;
        float var = g_sumsq[tid] * inv_n - mu * mu;
        float sc = bng[tid] * rsqrtf(var + 1e-5f);
        s_scale[tid] = sc;
        s_shift[tid] = bnb[tid] - mu * sc;
    }

    {
        const uint4* gLh = (const uint4*)(g_Wbf + (size_t)(wimgL * 2 + 0) * 128 * KPAD);
        const uint4* gLl = (const uint4*)(g_Wbf + (size_t)(wimgL * 2 + 1) * 128 * KPAD);
        const uint4* gRh = (const uint4*)(g_Wbf + (size_t)(wimgR * 2 + 0) * 128 * KPAD);
        const uint4* gRl = (const uint4*)(g_Wbf + (size_t)(wimgR * 2 + 1) * 128 * KPAD);
        uint4* sBh = (uint4*)(smem + DSM_BH);
        uint4* sBl = (uint4*)(smem + DSM_BL);
        for (int f = tid; f < 2176; f += 512) {
            sBh[f] = gLh[f];
            sBh[f + 2176] = gRh[f];
            sBl[f] = gLl[f];
            sBl[f + 2176] = gRl[f];
        }
    }

    float4 pre[2];
#pragma unroll
    for (int i = 0; i < 2; i++) {
        int f = tid + i * 512;
        int row = f >> 3, c4 = (f & 7) * 4;
        int gr = row0 + row;
        pre[i] = (gr < n) ? *(const float4*)&X[(size_t)gr * 128 + c4]
                          : make_float4(0.f, 0.f, 0.f, 0.f);
    }
    __syncthreads();

    float acc[2][8][4];
#pragma unroll
    for (int a = 0; a < 2; a++)
#pragma unroll
        for (int b = 0; b < 8; b++)
#pragma unroll
            for (int c = 0; c < 4; c++) acc[a][b][c] = 0.0f;

    const uint32_t aAh = sb + DSM_AH + (warp_m * 32 + (lane & 15)) * APADB + (lane >> 4) * 16;
    const uint32_t aAl = aAh + (DSM_AL - DSM_AH);
    const uint32_t aBh = sb + DSM_BH + (warp_n >> 1) * WIMG_BYTES
                       + ((warp_n & 1) * 64 + (lane & 7) + (lane >> 4) * 8) * (KPAD * 2)
                       + ((lane >> 3) & 1) * 16;
    const uint32_t aBl = aBh + (DSM_BL - DSM_BH);

    for (int kc = 0; kc < 128; kc += 32) {
#pragma unroll
        for (int i = 0; i < 2; i++) {
            int f = tid + i * 512;
            int row = f >> 3, c4 = (f & 7) * 4;
            float4 v = pre[i];
            if (mode == 2) {
                int cc = kc + c4;
                v.x = fmaxf(0.f, fmaf(v.x, s_scale[cc],     s_shift[cc]));
                v.y = fmaxf(0.f, fmaf(v.y, s_scale[cc + 1], s_shift[cc + 1]));
                v.z = fmaxf(0.f, fmaf(v.z, s_scale[cc + 2], s_shift[cc + 2]));
                v.w = fmaxf(0.f, fmaf(v.w, s_scale[cc + 3], s_shift[cc + 3]));
            }
            *(uint2*)(smem + DSM_AH + row * APADB + c4 * 2) =
                make_uint2(pack_hi(v.x, v.y), pack_hi(v.z, v.w));
            *(uint2*)(smem + DSM_AL + row * APADB + c4 * 2) =
                make_uint2(pack_lo(v.x, v.y), pack_lo(v.z, v.w));
        }
        __syncthreads();

        if (kc < 96) {
#pragma unroll
            for (int i = 0; i < 2; i++) {
                int f = tid + i * 512;
                int row = f >> 3, c4 = (f & 7) * 4;
                int gr = row0 + row;
                pre[i] = (gr < n) ? *(const float4*)&X[(size_t)gr * 128 + kc + 32 + c4]
                                  : make_float4(0.f, 0.f, 0.f, 0.f);
            }
        }

#pragma unroll
        for (int kk = 0; kk < 32; kk += 16) {
            uint32_t ah[2][4], al[2][4];
#pragma unroll
            for (int ms = 0; ms < 2; ms++) {
                uint32_t off = ms * 16 * APADB + kk * 2;
                ldsm_x4(ah[ms][0], ah[ms][1], ah[ms][2], ah[ms][3], aAh + off);
                ldsm_x4(al[ms][0], al[ms][1], al[ms][2], al[ms][3], aAl + off);
            }
#pragma unroll
            for (int nn = 0; nn < 4; nn++) {
                uint32_t bh2[4], bl2[4];
                uint32_t off = nn * 16 * (KPAD * 2) + (kc + kk) * 2;
                ldsm_x4(bh2[0], bh2[1], bh2[2], bh2[3], aBh + off);
                ldsm_x4(bl2[0], bl2[1], bl2[2], bl2[3], aBl + off);
#pragma unroll
                for (int ms = 0; ms < 2; ms++) {
                    mma_bf16(acc[ms][nn * 2],     ah[ms], bh2);
                    mma_bf16(acc[ms][nn * 2],     al[ms], bh2);
                    mma_bf16(acc[ms][nn * 2],     ah[ms], bl2);
                    mma_bf16(acc[ms][nn * 2 + 1], ah[ms], bh2 + 2);
                    mma_bf16(acc[ms][nn * 2 + 1], al[ms], bh2 + 2);
                    mma_bf16(acc[ms][nn * 2 + 1], ah[ms], bl2 + 2);
                }
            }
        }
        if (kc < 96) __syncthreads();
    }

    float* Y = (warp_n < 2) ? YL : YR;
    const float* bias = (warp_n < 2) ? biasL : biasR;
    const int er0 = row0 + warp_m * 32 + (lane >> 2);
    const int ec0 = (warp_n & 1) * 64 + (lane & 3) * 2;
#pragma unroll
    for (int ms = 0; ms < 2; ms++) {
#pragma unroll
        for (int ns = 0; ns < 8; ns++) {
            int r = er0 + ms * 16;
            int c = ec0 + ns * 8;
            float b0 = __ldg(&bias[c]), b1 = __ldg(&bias[c + 1]);
            if (r < n)
                *(float2*)&Y[(size_t)r * 128 + c] =
                    make_float2(acc[ms][ns][0] + b0, acc[ms][ns][1] + b1);
            if (r + 8 < n)
                *(float2*)&Y[(size_t)(r + 8) * 128 + c] =
                    make_float2(acc[ms][ns][2] + b0, acc[ms][ns][3] + b1);
        }
    }
}

// ---------------- GEMM v5 (residual + fused BN stats): Y = X + X@W + b ----------------
#define SM4_AH 0
#define SM4_AL 10240
#define SM4_BH 20480
#define SM4_BL 55296
#define SM4_TOTAL 90112

__global__ __launch_bounds__(256, 2) void gemm_mma4_kernel(
    const float* __restrict__ X, int wimg, const float* __restrict__ bias,
    float* __restrict__ Y, int n)
{
    extern __shared__ char smem[];
    const uint32_t sb = smem_to_u32(smem);
    const int tid = threadIdx.x;
    const int wid = tid >> 5;
    const int lane = tid & 31;
    const int row0 = blockIdx.x * 128;
    const int warp_m = wid & 3;
    const int warp_n = wid >> 2;

    {
        const uint4* gBh = (const uint4*)(g_Wbf + (size_t)(wimg * 2 + 0) * 128 * KPAD);
        const uint4* gBl = (const uint4*)(g_Wbf + (size_t)(wimg * 2 + 1) * 128 * KPAD);
        uint4* sBh = (uint4*)(smem + SM4_BH);
        uint4* sBl = (uint4*)(smem + SM4_BL);
        for (int f = tid; f < 2176; f += 256) {
            sBh[f] = gBh[f];
            sBl[f] = gBl[f];
        }
    }

    float4 pre[4];
#pragma unroll
    for (int i = 0; i < 4; i++) {
        int f = tid + i * 256;
        int row = f >> 3, c4 = (f & 7) * 4;
        int gr = row0 + row;
        pre[i] = (gr < n) ? *(const float4*)&X[(size_t)gr * 128 + c4]
                          : make_float4(0.f, 0.f, 0.f, 0.f);
    }
    __syncthreads();

    float acc[2][8][4];
#pragma unroll
    for (int a = 0; a < 2; a++)
#pragma unroll
        for (int b = 0; b < 8; b++)
#pragma unroll
            for (int c = 0; c < 4; c++) acc[a][b][c] = 0.0f;

    const uint32_t aAh = sb + SM4_AH + (warp_m * 32 + (lane & 15)) * APADB + (lane >> 4) * 16;
    const uint32_t aAl = aAh + (SM4_AL - SM4_AH);
    const uint32_t aBh = sb + SM4_BH + (warp_n * 64 + (lane & 7) + (lane >> 4) * 8) * (KPAD * 2)
                       + ((lane >> 3) & 1) * 16;
    const uint32_t aBl = aBh + (SM4_BL - SM4_BH);

    for (int kc = 0; kc < 128; kc += 32) {
#pragma unroll
        for (int i = 0; i < 4; i++) {
            int f = tid + i * 256;
            int row = f >> 3, c4 = (f & 7) * 4;
            float4 v = pre[i];
            *(uint2*)(smem + SM4_AH + row * APADB + c4 * 2) =
                make_uint2(pack_hi(v.x, v.y), pack_hi(v.z, v.w));
            *(uint2*)(smem + SM4_AL + row * APADB + c4 * 2) =
                make_uint2(pack_lo(v.x, v.y), pack_lo(v.z, v.w));
        }
        __syncthreads();

        if (kc < 96) {
#pragma unroll
            for (int i = 0; i < 4; i++) {
                int f = tid + i * 256;
                int row = f >> 3, c4 = (f & 7) * 4;
                int gr = row0 + row;
                pre[i] = (gr < n) ? *(const float4*)&X[(size_t)gr * 128 + kc + 32 + c4]
                                  : make_float4(0.f, 0.f, 0.f, 0.f);
            }
        }

#pragma unroll
        for (int kk = 0; kk < 32; kk += 16) {
            uint32_t ah[2][4], al[2][4];
#pragma unroll
            for (int ms = 0; ms < 2; ms++) {
                uint32_t off = ms * 16 * APADB + kk * 2;
                ldsm_x4(ah[ms][0], ah[ms][1], ah[ms][2], ah[ms][3], aAh + off);
                ldsm_x4(al[ms][0], al[ms][1], al[ms][2], al[ms][3], aAl + off);
            }
#pragma unroll
            for (int nn = 0; nn < 4; nn++) {
                uint32_t bh2[4], bl2[4];
                uint32_t off = nn * 16 * (KPAD * 2) + (kc + kk) * 2;
                ldsm_x4(bh2[0], bh2[1], bh2[2], bh2[3], aBh + off);
                ldsm_x4(bl2[0], bl2[1], bl2[2], bl2[3], aBl + off);
#pragma unroll
                for (int ms = 0; ms < 2; ms++) {
                    mma_bf16(acc[ms][nn * 2],     ah[ms], bh2);
                    mma_bf16(acc[ms][nn * 2],     al[ms], bh2);
                    mma_bf16(acc[ms][nn * 2],     ah[ms], bl2);
                    mma_bf16(acc[ms][nn * 2 + 1], ah[ms], bh2 + 2);
                    mma_bf16(acc[ms][nn * 2 + 1], al[ms], bh2 + 2);
                    mma_bf16(acc[ms][nn * 2 + 1], ah[ms], bl2 + 2);
                }
            }
        }
        if (kc < 96) __syncthreads();
    }

    // epilogue with fused BN stats (column sum / sumsq)
    float cs[16], cq[16];
#pragma unroll
    for (int j = 0; j < 16; j++) { cs[j] = 0.f; cq[j] = 0.f; }

    const int er0 = row0 + warp_m * 32 + (lane >> 2);
    const int ec0 = warp_n * 64 + (lane & 3) * 2;
#pragma unroll
    for (int ms = 0; ms < 2; ms++) {
#pragma unroll
        for (int ns = 0; ns < 8; ns++) {
            int r = er0 + ms * 16;
            int c = ec0 + ns * 8;
            float b0 = __ldg(&bias[c]), b1 = __ldg(&bias[c + 1]);
            if (r < n) {
                const float2 rv = *(const float2*)&X[(size_t)r * 128 + c];
                float o0 = acc[ms][ns][0] + b0 + rv.x;
                float o1 = acc[ms][ns][1] + b1 + rv.y;
                *(float2*)&Y[(size_t)r * 128 + c] = make_float2(o0, o1);
                cs[ns * 2] += o0; cq[ns * 2] += o0 * o0;
                cs[ns * 2 + 1] += o1; cq[ns * 2 + 1] += o1 * o1;
            }
            if (r + 8 < n) {
                const float2 rv = *(const float2*)&X[(size_t)(r + 8) * 128 + c];
                float o0 = acc[ms][ns][2] + b0 + rv.x;
                float o1 = acc[ms][ns][3] + b1 + rv.y;
                *(float2*)&Y[(size_t)(r + 8) * 128 + c] = make_float2(o0, o1);
                cs[ns * 2] += o0; cq[ns * 2] += o0 * o0;
                cs[ns * 2 + 1] += o1; cq[ns * 2 + 1] += o1 * o1;
            }
        }
    }

#pragma unroll
    for (int o = 4; o <= 16; o <<= 1) {
#pragma unroll
        for (int j = 0; j < 16; j++) {
            cs[j] += __shfl_xor_sync(0xffffffff, cs[j], o);
            cq[j] += __shfl_xor_sync(0xffffffff, cq[j], o);
        }
    }
    __syncthreads();
    float (*sred)[4][32] = (float (*)[4][32])(smem + SM4_AH);
    if (lane < 4) {
#pragma unroll
        for (int j = 0; j < 16; j++) {
            sred[wid][lane][j] = cs[j];
            sred[wid][lane][16 + j] = cq[j];
        }
    }
    __syncthreads();
    {
        int stat = tid >> 7;
        int col = tid & 127;
        int wn = col >> 6;
        int lane_sel = (col >> 1) & 3;
        int nss = (col & 63) >> 3;
        int j0 = nss * 2 + (col & 1);
        int idx = stat * 16 + j0;
        float t = sred[wn * 4 + 0][lane_sel][idx] + sred[wn * 4 + 1][lane_sel][idx]
                + sred[wn * 4 + 2][lane_sel][idx] + sred[wn * 4 + 3][lane_sel][idx];
        if (stat == 0) atomicAdd(&g_sum[col], t);
        else           atomicAdd(&g_sumsq[col], t);
    }
}

// ---------------- CSR build ------------------------------------------------------
__global__ void csr_hist_kernel(const int* __restrict__ dst, int E) {
    int e = blockIdx.x * blockDim.x + threadIdx.x;
    if (e < E) atomicAdd(&g_deg[dst[e]], 1);
}
__global__ void csr_scanA_kernel(int n) {
    __shared__ int s[1024];
    int t = threadIdx.x;
    int i = blockIdx.x * 1024 + t;
    int v = (i < n) ? g_deg[i] : 0;
    s[t] = v;
    __syncthreads();
#pragma unroll
    for (int off = 1; off < 1024; off <<= 1) {
        int x = (t >= off) ? s[t - off] : 0;
        __syncthreads();
        s[t] += x;
        __syncthreads();
    }
    if (i < n) g_rowptr[i + 1] = s[t];
    if (t == 1023) g_blocksum[blockIdx.x] = s[t];
    if (i == 0) g_rowptr[0] = 0;
}
__global__ void csr_scanC_kernel(int n) {
    __shared__ int s_off;
    int t = threadIdx.x;
    if (t < 32) {
        int b = blockIdx.x;
        int sum = 0;
        for (int i = t; i < b; i += 32) sum += g_blocksum[i];
#pragma unroll
        for (int o = 16; o; o >>= 1) sum += __shfl_xor_sync(0xffffffff, sum, o);
        if (t == 0) s_off = sum;
    }
    __syncthreads();
    int i = blockIdx.x * 1024 + t;
    if (i < n) g_rowptr[i + 1] += s_off;
}
__global__ void csr_fill_kernel(const int* __restrict__ src, const int* __restrict__ dst, int E) {
    int e = blockIdx.x * blockDim.x + threadIdx.x;
    if (e < E) {
        int d = dst[e];
        int pos = g_rowptr[d] + atomicAdd(&g_fill[d], 1);
        g_col[pos] = src[e];
    }
}

// ---------------- aggregation v3 (R10/R14): warp/node, 2-deep gather prefetch ---------
__device__ __forceinline__ float dot_leaky(float4 xs4, float4 xd4, float4 at4) {
    float t, p = 0.0f;
    t = xs4.x + xd4.x; t = t > 0.f ? t : NEG_SLOPE * t; p = fmaf(t, at4.x, p);
    t = xs4.y + xd4.y; t = t > 0.f ? t : NEG_SLOPE * t; p = fmaf(t, at4.y, p);
    t = xs4.z + xd4.z; t = t > 0.f ? t : NEG_SLOPE * t; p = fmaf(t, at4.z, p);
    t = xs4.w + xd4.w; t = t > 0.f ? t : NEG_SLOPE * t; p = fmaf(t, at4.w, p);
    return p;
}

__global__ __launch_bounds__(256) void agg_kernel(
    const float* __restrict__ att, const float* __restrict__ cb, int n)
{
    if (blockIdx.x == 0 && threadIdx.x < HDIM) {
        g_sum[threadIdx.x] = 0.0f;
        g_sumsq[threadIdx.x] = 0.0f;
    }
    int d = (blockIdx.x * blockDim.x + threadIdx.x) >> 5;
    int lane = threadIdx.x & 31;
    if (d >= n) return;

    float4 xd4 = *(const float4*)&g_xd[(size_t)d * 128 + lane * 4];
    float4 at4 = *(const float4*)&att[lane * 4];
    int e0 = g_rowptr[d], e1 = g_rowptr[d + 1];

    float den = 0.0f;
    float4 acc = make_float4(0.f, 0.f, 0.f, 0.f);

    if (e0 < e1) {
        int s0 = g_col[e0];
        int s1 = (e0 + 1 < e1) ? g_col[e0 + 1] : s0;
        float4 a0 = *(const float4*)&g_xs[(size_t)s0 * 128 + lane * 4];
        float4 a1 = *(const float4*)&g_xs[(size_t)s1 * 128 + lane * 4];

        for (int e = e0; e < e1; e += 2) {
            float4 c0 = a0, c1 = a1;
            bool v1 = (e + 1 < e1);
            if (e + 2 < e1) {
                int t0 = g_col[e + 2];
                int t1 = (e + 3 < e1) ? g_col[e + 3] : t0;
                a0 = *(const float4*)&g_xs[(size_t)t0 * 128 + lane * 4];
                a1 = *(const float4*)&g_xs[(size_t)t1 * 128 + lane * 4];
            }
            float p0 = dot_leaky(c0, xd4, at4);
            float p1 = dot_leaky(c1, xd4, at4);
#pragma unroll
            for (int o = 16; o; o >>= 1) {
                p0 += __shfl_xor_sync(0xffffffff, p0, o);
                p1 += __shfl_xor_sync(0xffffffff, p1, o);
            }
            float w0 = __expf(p0);
            float w1 = v1 ? __expf(p1) : 0.0f;
            den += w0 + w1;
            acc.x = fmaf(w0, c0.x, fmaf(w1, c1.x, acc.x));
            acc.y = fmaf(w0, c0.y, fmaf(w1, c1.y, acc.y));
            acc.z = fmaf(w0, c0.z, fmaf(w1, c1.z, acc.z));
            acc.w = fmaf(w0, c0.w, fmaf(w1, c1.w, acc.w));
        }
    }

    float inv = 1.0f / (den + 1e-16f);
    float4 cb4 = *(const float4*)&cb[lane * 4];
    float4 o;
    o.x = acc.x * inv + cb4.x;
    o.y = acc.y * inv + cb4.y;
    o.z = acc.z * inv + cb4.z;
    o.w = acc.w * inv + cb4.w;
    *(float4*)&g_acc[(size_t)d * 128 + lane * 4] = o;
}

// ---------------- BN apply (final output, float4) ---------------------------------------
__global__ __launch_bounds__(256) void bn_apply_kernel(
    const float* __restrict__ gamma, const float* __restrict__ beta,
    float* __restrict__ out, int n)
{
    int i = blockIdx.x * blockDim.x + threadIdx.x;       // one float4 per thread
    if (i >= n * 32) return;
    int h4 = (i & 31) * 4;
    float inv_n = 1.0f / (float)n;
    float4 v = *(const float4*)&g_h[(size_t)i * 4];
    float4 o;
#pragma unroll
    for (int j = 0; j < 4; j++) {
        int h = h4 + j;
        float mu = g_sum[h] * inv_n;
        float var = g_sumsq[h] * inv_n - mu * mu;
        float val = ((&v.x)[j] - mu) * rsqrtf(var + 1e-5f) * gamma[h] + beta[h];
        (&o.x)[j] = val;
    }
    *(float4*)&out[(size_t)i * 4] = o;
}

// ---------------- host driver ---------------------------------------------------------
extern "C" void kernel_launch(void* const* d_in, const int* in_sizes, int n_in,
                              void* d_out, int out_size)
{
    const float* x     = (const float*)d_in[0];
    const int*   ei    = (const int*)  d_in[1];
    const float* Wl    = (const float*)d_in[2];
    const float* bl    = (const float*)d_in[3];
    const float* Wr    = (const float*)d_in[4];
    const float* br    = (const float*)d_in[5];
    const float* att   = (const float*)d_in[6];
    const float* cb    = (const float*)d_in[7];
    const float* Wlin  = (const float*)d_in[8];
    const float* blin  = (const float*)d_in[9];
    const float* gamma = (const float*)d_in[10];
    const float* beta  = (const float*)d_in[11];

    const int n = in_sizes[0] / HDIM;
    const int E = in_sizes[1] / 2;
    const int* src = ei;
    const int* dst = ei + E;

    void* p;
    cudaGetSymbolAddress(&p, g_acc); float* p_acc = (float*)p;
    cudaGetSymbolAddress(&p, g_xs);  float* p_xs  = (float*)p;
    cudaGetSymbolAddress(&p, g_xd);  float* p_xd  = (float*)p;
    cudaGetSymbolAddress(&p, g_h);   float* p_h   = (float*)p;

    static cudaStream_t s2 = nullptr;
    static cudaEvent_t ev_fork = nullptr, ev_join = nullptr;
    if (!s2) {
        cudaStreamCreateWithFlags(&s2, cudaStreamNonBlocking);
        cudaEventCreateWithFlags(&ev_fork, cudaEventDisableTiming);
        cudaEventCreateWithFlags(&ev_join, cudaEventDisableTiming);
        cudaFuncSetAttribute(gemm_mma4_kernel, cudaFuncAttributeMaxDynamicSharedMemorySize,
                             SM4_TOTAL);
        cudaFuncSetAttribute(gemm_dual_kernel, cudaFuncAttributeMaxDynamicSharedMemorySize,
                             DSM_TOTAL);
    }

    const int gemm_blocks = (n + 127) / 128;
    const int agg_blocks  = (n + 7) / 8;
    const int e_blocks    = (E + 255) / 256;
    const int scan_blocks = (n + 1023) / 1024;
    const int prep_blocks = (6 * 128 * 128 + 255) / 256;
    const int bn4_blocks  = (n * 32 + 255) / 256;

    // fork: CSR build on side stream, overlapped with prep_w + layer-0 dual GEMM
    cudaEventRecord(ev_fork, 0);
    cudaStreamWaitEvent(s2, ev_fork, 0);
    csr_zero_kernel<<<(n + 255) / 256, 256, 0, s2>>>(n);
    csr_hist_kernel<<<e_blocks, 256, 0, s2>>>(dst, E);
    csr_scanA_kernel<<<scan_blocks, 1024, 0, s2>>>(n);
    csr_scanC_kernel<<<scan_blocks, 1024, 0, s2>>>(n);
    csr_fill_kernel<<<e_blocks, 256, 0, s2>>>(src, dst, E);
    cudaEventRecord(ev_join, s2);

    // main stream: weight prep + layer-0 transforms
    prep_w_kernel<<<prep_blocks, 256>>>(Wl, Wr, Wlin, n);
    gemm_dual_kernel<<<gemm_blocks, 512, DSM_TOTAL>>>(x, 0, 1, bl, br, p_xs, p_xd,
                                                      n, 0, nullptr, nullptr);

    // join: agg needs the CSR
    cudaStreamWaitEvent(0, ev_join, 0);

    // layer 0
    agg_kernel<<<agg_blocks, 256>>>(att, cb, n);
    gemm_mma4_kernel<<<gemm_blocks, 256, SM4_TOTAL>>>(p_acc, 2, blin, p_h, n);

    // layer 1 (BN+relu of layer-0 output fused into dual A-staging)
    gemm_dual_kernel<<<gemm_blocks, 512, DSM_TOTAL>>>(p_h, 3, 4, bl + HDIM, br + HDIM,
                                                      p_xs, p_xd, n, 2, gamma, beta);
    agg_kernel<<<agg_blocks, 256>>>(att + HDIM, cb + HDIM, n);
    gemm_mma4_kernel<<<gemm_blocks, 256, SM4_TOTAL>>>(p_acc, 5, blin + HDIM, p_h, n);
    bn_apply_kernel<<<bn4_blocks, 256>>>(gamma + HDIM, beta + HDIM, (float*)d_out, n);
}